// round 10
// baseline (speedup 1.0000x reference)
#include <cuda_runtime.h>
#include <cuda_bf16.h>
#include <math.h>
#include <stdint.h>

#define BS    4
#define SEQ   2048
#define DIM   1024
#define NHEAD 8
#define DH    128
#define BH    (BS*NHEAD)
#define NEG_INF_F (-1e9f)

// ---------------- scratch (device globals; no runtime allocation) ----------------
__device__ float g_Q[(size_t)BS*NHEAD*SEQ*DH];      // 32 MB
__device__ float g_K[(size_t)BS*NHEAD*SEQ*DH];      // 32 MB
__device__ float g_V[(size_t)BS*NHEAD*SEQ*DH];      // 32 MB
__device__ float g_Y[(size_t)BS*SEQ*DIM];           // 32 MB
__device__ float g_AP[(size_t)SEQ*SEQ];             // 16 MB
__device__ float g_E[(size_t)BS*NHEAD*SEQ*SEQ];     // 512 MB
__device__ double g_invf[1024];                     // i in [0, SEQ/2)

// ---------------- helpers ----------------
__device__ __forceinline__ uint32_t pack_hi(float x, float y) {
    __nv_bfloat162 h = __floats2bfloat162_rn(x, y);
    return *reinterpret_cast<uint32_t*>(&h);
}
__device__ __forceinline__ uint32_t pack_lo(float x, float y, uint32_t hi) {
    __nv_bfloat162 h = *reinterpret_cast<__nv_bfloat162*>(&hi);
    __nv_bfloat162 l = __floats2bfloat162_rn(x - __bfloat162float(h.x),
                                             y - __bfloat162float(h.y));
    return *reinterpret_cast<uint32_t*>(&l);
}

__device__ __forceinline__ void mma16(float* c, const uint32_t* a, const uint32_t* b) {
    asm volatile(
        "mma.sync.aligned.m16n8k16.row.col.f32.bf16.bf16.f32 "
        "{%0,%1,%2,%3}, {%4,%5,%6,%7}, {%8,%9}, {%0,%1,%2,%3};\n"
        : "+f"(c[0]), "+f"(c[1]), "+f"(c[2]), "+f"(c[3])
        : "r"(a[0]), "r"(a[1]), "r"(a[2]), "r"(a[3]), "r"(b[0]), "r"(b[1]));
}

__device__ __forceinline__ void ldsm_x4(uint32_t* r, uint32_t addr) {
    asm volatile("ldmatrix.sync.aligned.m8n8.x4.shared.b16 {%0,%1,%2,%3}, [%4];"
                 : "=r"(r[0]), "=r"(r[1]), "=r"(r[2]), "=r"(r[3]) : "r"(addr));
}
__device__ __forceinline__ void ldsm_x2(uint32_t* r, uint32_t addr) {
    asm volatile("ldmatrix.sync.aligned.m8n8.x2.shared.b16 {%0,%1}, [%2];"
                 : "=r"(r[0]), "=r"(r[1]) : "r"(addr));
}

// ---------------- AP precompute ----------------
__global__ void invf_kernel() {
    int i = blockIdx.x * blockDim.x + threadIdx.x;
    if (i < 1024) g_invf[i] = exp(-(double)(2 * i) / 1024.0 * log(10000.0));
}
__global__ void ap_kernel() {
    int idx = blockIdx.x * blockDim.x + threadIdx.x;
    if (idx >= SEQ * SEQ) return;
    int q = idx >> 11;
    int k = idx & (SEQ - 1);
    double angle = (double)q * g_invf[k >> 1];
    const double TWO_PI = 6.283185307179586476925286766559;
    double t = floor(angle * (1.0 / TWO_PI));
    float a = (float)(angle - t * TWO_PI);
    g_AP[idx] = (k & 1) ? cosf(a) : sinf(a);
}

// ======================== NT tensor-core GEMM (3x bf16 compensated, ldmatrix) ========================
// C[M,N] = A[M,KC] * B[N,KC]^T ; smem holds PACKED bf16x2 hi/lo; ldmatrix frags.
// MODE 0: row-major store
// MODE 1: merged QKV: blockIdx.z selects weight and dest, scatter store
// MODE 2: QK^T per-head (blockIdx.z = bh) + AP + mask -> g_E   (2 CTAs/SM)
#define RS 20   // smem row stride in words (16 data + pad; ≡4 mod 32 → conflict-free)
template<int MODE, int KC>
__global__ __launch_bounds__(256, (MODE == 2) ? 2 : 1)
void gemm_nt_tc(const float* __restrict__ Ag, const float* __restrict__ Bg,
                float* __restrict__ Cg, int M, int N,
                const int* __restrict__ mask,
                const float* __restrict__ W1, const float* __restrict__ W2)
{
    __shared__ __align__(16) uint32_t AhiS[128 * RS];
    __shared__ __align__(16) uint32_t AloS[128 * RS];
    __shared__ __align__(16) uint32_t BhiS[128 * RS];
    __shared__ __align__(16) uint32_t BloS[128 * RS];
    __shared__ int maskS[(MODE == 2) ? 256 : 4];

    const int tid  = threadIdx.x;
    const int lane = tid & 31;
    const int wid  = tid >> 5;
    const int g    = lane >> 2;
    const int tig  = lane & 3;
    const int warp_m = wid & 1;    // 2 warp rows of 64
    const int warp_n = wid >> 1;   // 4 warp cols of 32

    const int m0 = blockIdx.y * 128;
    const int n0 = blockIdx.x * 128;

    const float* A = Ag;
    const float* B = Bg;
    float* Cd = Cg;
    int bh = 0, bb = 0;
    if (MODE == 1) {
        int z = blockIdx.z;
        B  = (z == 0) ? Bg : (z == 1) ? W1 : W2;
        Cd = (z == 0) ? g_Q : (z == 1) ? g_K : g_V;
    }
    if (MODE == 2) {
        bh = blockIdx.z;
        bb = bh >> 3;
        A = g_Q + (size_t)bh * SEQ * DH;
        B = g_K + (size_t)bh * SEQ * DH;
        // preload mask rows/cols for this tile into smem
        if (tid < 128)      maskS[tid]       = mask[bb * SEQ + m0 + tid];
        else if (tid < 256) maskS[tid]       = mask[bb * SEQ + n0 + tid - 128];
    }

    float acc[4][4][4];
#pragma unroll
    for (int i = 0; i < 4; i++)
#pragma unroll
        for (int j = 0; j < 4; j++)
#pragma unroll
            for (int r = 0; r < 4; r++) acc[i][j][r] = 0.f;

    const int ldr = tid >> 3;          // 0..31 (+r*32)
    const int ldc = (tid & 7) * 4;     // float col (4-wide) within 32-k chunk
    const int wc  = (tid & 7) * 2;     // word col

    // ldmatrix lane addressing (canonical non-trans mapping)
    const uint32_t AhiB = (uint32_t)__cvta_generic_to_shared(AhiS);
    const uint32_t AloB = (uint32_t)__cvta_generic_to_shared(AloS);
    const uint32_t BhiB = (uint32_t)__cvta_generic_to_shared(BhiS);
    const uint32_t BloB = (uint32_t)__cvta_generic_to_shared(BloS);
    const int a_row  = lane & 15;
    const int a_koff = (lane >> 4) << 2;
    const int b_row  = lane & 7;
    const int b_koff = ((lane >> 3) & 1) << 2;

    auto loadg = [&](int k0, float4* pa, float4* pb) {
#pragma unroll
        for (int r = 0; r < 4; r++) {
            int row = ldr + r * 32;
            pa[r] = *(const float4*)&A[(size_t)(m0 + row) * KC + k0 + ldc];
            pb[r] = *(const float4*)&B[(size_t)(n0 + row) * KC + k0 + ldc];
        }
    };
    auto stores = [&](const float4* pa, const float4* pb) {
#pragma unroll
        for (int r = 0; r < 4; r++) {
            int row = ldr + r * 32;
            float4 va = pa[r], vb = pb[r];
            uint32_t ah0 = pack_hi(va.x, va.y), ah1 = pack_hi(va.z, va.w);
            uint32_t al0 = pack_lo(va.x, va.y, ah0), al1 = pack_lo(va.z, va.w, ah1);
            uint32_t bh0 = pack_hi(vb.x, vb.y), bh1 = pack_hi(vb.z, vb.w);
            uint32_t bl0 = pack_lo(vb.x, vb.y, bh0), bl1 = pack_lo(vb.z, vb.w, bh1);
            *(uint2*)&AhiS[row * RS + wc] = make_uint2(ah0, ah1);
            *(uint2*)&AloS[row * RS + wc] = make_uint2(al0, al1);
            *(uint2*)&BhiS[row * RS + wc] = make_uint2(bh0, bh1);
            *(uint2*)&BloS[row * RS + wc] = make_uint2(bl0, bl1);
        }
    };

    float4 pa[4], pb[4];
    loadg(0, pa, pb);
    stores(pa, pb);
    __syncthreads();

#pragma unroll ((KC == 128) ? 4 : 1)
    for (int k0 = 0; k0 < KC; k0 += 32) {
        const bool more = (k0 + 32 < KC);
        float4 na[4], nb[4];
        if (more) loadg(k0 + 32, na, nb);

#pragma unroll
        for (int ks = 0; ks < 2; ks++) {
            const int wb = ks * 8;     // word base of this k16 step
            uint32_t ahf[4][4], alf[4][4], bhf[4][2], blf[4][2];
#pragma unroll
            for (int tm = 0; tm < 4; tm++) {
                int mr = warp_m * 64 + tm * 16;
                uint32_t off = (uint32_t)(((mr + a_row) * RS + wb + a_koff) * 4);
                ldsm_x4(ahf[tm], AhiB + off);
                ldsm_x4(alf[tm], AloB + off);
            }
#pragma unroll
            for (int tn = 0; tn < 4; tn++) {
                int nr = warp_n * 32 + tn * 8;
                uint32_t off = (uint32_t)(((nr + b_row) * RS + wb + b_koff) * 4);
                ldsm_x2(bhf[tn], BhiB + off);
                ldsm_x2(blf[tn], BloB + off);
            }
#pragma unroll
            for (int tm = 0; tm < 4; tm++)
#pragma unroll
                for (int tn = 0; tn < 4; tn++) {
                    mma16(acc[tm][tn], ahf[tm], bhf[tn]);
                    mma16(acc[tm][tn], ahf[tm], blf[tn]);
                    mma16(acc[tm][tn], alf[tm], bhf[tn]);
                }
        }

        __syncthreads();
        if (more) {
            stores(na, nb);
            __syncthreads();
        }
    }

    // ---------------- epilogue ----------------
    if (MODE == 0) {
#pragma unroll
        for (int tm = 0; tm < 4; tm++) {
#pragma unroll
            for (int tn = 0; tn < 4; tn++) {
                int row0 = m0 + warp_m * 64 + tm * 16 + g;
                int col  = n0 + warp_n * 32 + tn * 8 + 2 * tig;
                *(float2*)&Cd[(size_t)row0 * N + col]       = make_float2(acc[tm][tn][0], acc[tm][tn][1]);
                *(float2*)&Cd[(size_t)(row0 + 8) * N + col] = make_float2(acc[tm][tn][2], acc[tm][tn][3]);
            }
        }
    } else if (MODE == 1) {
#pragma unroll
        for (int tm = 0; tm < 4; tm++) {
#pragma unroll
            for (int tn = 0; tn < 4; tn++) {
                int col = n0 + warp_n * 32 + tn * 8 + 2 * tig;
                int h = col >> 7, e = col & (DH - 1);
#pragma unroll
                for (int half = 0; half < 2; half++) {
                    int row = m0 + warp_m * 64 + tm * 16 + g + half * 8;
                    int b = row >> 11, nr = row & (SEQ - 1);
                    *(float2*)&Cd[(((size_t)b * NHEAD + h) * SEQ + nr) * DH + e] =
                        make_float2(acc[tm][tn][2 * half], acc[tm][tn][2 * half + 1]);
                }
            }
        }
    } else { // MODE == 2: QK^T epilogue
        float* Ep = g_E + (size_t)bh * SEQ * SEQ;
#pragma unroll
        for (int tm = 0; tm < 4; tm++) {
#pragma unroll
            for (int half = 0; half < 2; half++) {
                int qi = warp_m * 64 + tm * 16 + g + half * 8;   // local row
                int q = m0 + qi;
                int mq = maskS[qi];
#pragma unroll
                for (int tn = 0; tn < 4; tn++) {
                    int ci = warp_n * 32 + tn * 8 + 2 * tig;      // local col
                    int c = n0 + ci;
                    int mk0 = maskS[128 + ci];
                    int mk1 = maskS[128 + ci + 1];
                    float2 ap = *(const float2*)&g_AP[(size_t)q * SEQ + c];
                    float v0 = (mq && mk0) ? acc[tm][tn][2 * half]     + ap.x : NEG_INF_F;
                    float v1 = (mq && mk1) ? acc[tm][tn][2 * half + 1] + ap.y : NEG_INF_F;
                    *(float2*)&Ep[(size_t)q * SEQ + c] = make_float2(v0, v1);
                }
            }
        }
    }
}

// ======================== softmax (float4) ========================
__global__ __launch_bounds__(256)
void softmax_kernel(float* __restrict__ att_out, int write_att)
{
    int row = blockIdx.x;
    float4* Ep4 = (float4*)(g_E + (size_t)row * SEQ);
    int tid = threadIdx.x;

    __shared__ float shm[8];
    __shared__ float shs[8];

    float4 u0 = Ep4[tid];
    float4 u1 = Ep4[tid + 256];
    float mx = fmaxf(fmaxf(fmaxf(u0.x, u0.y), fmaxf(u0.z, u0.w)),
                     fmaxf(fmaxf(u1.x, u1.y), fmaxf(u1.z, u1.w)));
#pragma unroll
    for (int o = 16; o > 0; o >>= 1) mx = fmaxf(mx, __shfl_xor_sync(0xffffffffu, mx, o));
    int w = tid >> 5, l = tid & 31;
    if (l == 0) shm[w] = mx;
    __syncthreads();
    float rmax = shm[0];
#pragma unroll
    for (int i = 1; i < 8; i++) rmax = fmaxf(rmax, shm[i]);

    u0.x = expf(u0.x - rmax); u0.y = expf(u0.y - rmax);
    u0.z = expf(u0.z - rmax); u0.w = expf(u0.w - rmax);
    u1.x = expf(u1.x - rmax); u1.y = expf(u1.y - rmax);
    u1.z = expf(u1.z - rmax); u1.w = expf(u1.w - rmax);
    float s = (u0.x + u0.y + u0.z + u0.w) + (u1.x + u1.y + u1.z + u1.w);
#pragma unroll
    for (int o = 16; o > 0; o >>= 1) s += __shfl_xor_sync(0xffffffffu, s, o);
    if (l == 0) shs[w] = s;
    __syncthreads();
    float rsum = 0.f;
#pragma unroll
    for (int i = 0; i < 8; i++) rsum += shs[i];

    float inv = 1.f / rsum;
    u0.x *= inv; u0.y *= inv; u0.z *= inv; u0.w *= inv;
    u1.x *= inv; u1.y *= inv; u1.z *= inv; u1.w *= inv;

    Ep4[tid]       = u0;
    Ep4[tid + 256] = u1;

    int h = (row >> 11) & (NHEAD - 1);
    if (write_att && h == NHEAD - 1) {
        int b = row >> 14;
        int q = row & (SEQ - 1);
        float4* ap4 = (float4*)(att_out + ((size_t)b * SEQ + q) * SEQ);
        ap4[tid]       = u0;
        ap4[tid + 256] = u1;
    }
}

// ======================== A^T V (TN, 3x bf16 compensated, packed smem) ========================
// y[i,e] = sum_j A[j,i] * V[j,e] per bh; smem: [k_pair][m] packed bf16x2 (k,k+1)
#define MS 136  // m stride in words (128 + pad; ≡8 mod 32 → conflict-free fragment loads)
__global__ __launch_bounds__(256, 1)
void atv_tc()
{
    __shared__ __align__(16) uint32_t AhiS[16 * MS];
    __shared__ __align__(16) uint32_t AloS[16 * MS];
    __shared__ __align__(16) uint32_t BhiS[16 * MS];
    __shared__ __align__(16) uint32_t BloS[16 * MS];

    const int tid  = threadIdx.x;
    const int lane = tid & 31;
    const int wid  = tid >> 5;
    const int g    = lane >> 2;
    const int tig  = lane & 3;
    const int warp_m = wid & 1;
    const int warp_n = wid >> 1;

    const int bh = blockIdx.y;
    const int b = bh >> 3, h = bh & 7;
    const int m0 = blockIdx.x * 128;

    const float* Ap = g_E + (size_t)bh * SEQ * SEQ;
    const float* Vp = g_V + (size_t)bh * SEQ * DH;

    float acc[4][4][4];
#pragma unroll
    for (int i = 0; i < 4; i++)
#pragma unroll
        for (int j = 0; j < 4; j++)
#pragma unroll
            for (int r = 0; r < 4; r++) acc[i][j][r] = 0.f;

    const int pbase = tid >> 5;        // k-pair 0..7 (+8 second iter)
    const int mc    = (tid & 31) * 4;  // m/e column (4-wide)

    auto loadg = [&](int k0, float4* pa, float4* pb) {
#pragma unroll
        for (int r = 0; r < 2; r++) {
            int p = pbase + r * 8;
            pa[2 * r + 0] = *(const float4*)&Ap[(size_t)(k0 + 2 * p)     * SEQ + m0 + mc];
            pa[2 * r + 1] = *(const float4*)&Ap[(size_t)(k0 + 2 * p + 1) * SEQ + m0 + mc];
            pb[2 * r + 0] = *(const float4*)&Vp[(size_t)(k0 + 2 * p)     * DH + mc];
            pb[2 * r + 1] = *(const float4*)&Vp[(size_t)(k0 + 2 * p + 1) * DH + mc];
        }
    };
    auto stores = [&](const float4* pa, const float4* pb) {
#pragma unroll
        for (int r = 0; r < 2; r++) {
            int p = pbase + r * 8;
            float4 a0 = pa[2 * r], a1 = pa[2 * r + 1];
            float4 b0 = pb[2 * r], b1 = pb[2 * r + 1];
            uint32_t ah0 = pack_hi(a0.x, a1.x), ah1 = pack_hi(a0.y, a1.y);
            uint32_t ah2 = pack_hi(a0.z, a1.z), ah3 = pack_hi(a0.w, a1.w);
            uint32_t al0 = pack_lo(a0.x, a1.x, ah0), al1 = pack_lo(a0.y, a1.y, ah1);
            uint32_t al2 = pack_lo(a0.z, a1.z, ah2), al3 = pack_lo(a0.w, a1.w, ah3);
            uint32_t bh0 = pack_hi(b0.x, b1.x), bh1 = pack_hi(b0.y, b1.y);
            uint32_t bh2 = pack_hi(b0.z, b1.z), bh3 = pack_hi(b0.w, b1.w);
            uint32_t bl0 = pack_lo(b0.x, b1.x, bh0), bl1 = pack_lo(b0.y, b1.y, bh1);
            uint32_t bl2 = pack_lo(b0.z, b1.z, bh2), bl3 = pack_lo(b0.w, b1.w, bh3);
            *(uint4*)&AhiS[p * MS + mc] = make_uint4(ah0, ah1, ah2, ah3);
            *(uint4*)&AloS[p * MS + mc] = make_uint4(al0, al1, al2, al3);
            *(uint4*)&BhiS[p * MS + mc] = make_uint4(bh0, bh1, bh2, bh3);
            *(uint4*)&BloS[p * MS + mc] = make_uint4(bl0, bl1, bl2, bl3);
        }
    };

    float4 pa[4], pb[4];
    loadg(0, pa, pb);
    stores(pa, pb);
    __syncthreads();

    for (int k0 = 0; k0 < SEQ; k0 += 32) {
        const bool more = (k0 + 32 < SEQ);
        float4 na[4], nb[4];
        if (more) loadg(k0 + 32, na, nb);

#pragma unroll
        for (int ks = 0; ks < 2; ks++) {
            const int wb = ks * 8;    // k-pair base of this k16 step
            uint32_t ahf[4][4], alf[4][4], bhf[4][2], blf[4][2];
#pragma unroll
            for (int tm = 0; tm < 4; tm++) {
                int m = warp_m * 64 + tm * 16 + g;
                const uint32_t* ph = &AhiS[(wb + tig) * MS + m];
                const uint32_t* pl = &AloS[(wb + tig) * MS + m];
                ahf[tm][0] = ph[0];
                ahf[tm][1] = ph[8];
                ahf[tm][2] = ph[4 * MS];
                ahf[tm][3] = ph[4 * MS + 8];
                alf[tm][0] = pl[0];
                alf[tm][1] = pl[8];
                alf[tm][2] = pl[4 * MS];
                alf[tm][3] = pl[4 * MS + 8];
            }
#pragma unroll
            for (int tn = 0; tn < 4; tn++) {
                int n = warp_n * 32 + tn * 8 + g;
                const uint32_t* qh = &BhiS[(wb + tig) * MS + n];
                const uint32_t* ql = &BloS[(wb + tig) * MS + n];
                bhf[tn][0] = qh[0];
                bhf[tn][1] = qh[4 * MS];
                blf[tn][0] = ql[0];
                blf[tn][1] = ql[4 * MS];
            }
#pragma unroll
            for (int tm = 0; tm < 4; tm++)
#pragma unroll
                for (int tn = 0; tn < 4; tn++) {
                    mma16(acc[tm][tn], ahf[tm], bhf[tn]);
                    mma16(acc[tm][tn], ahf[tm], blf[tn]);
                    mma16(acc[tm][tn], alf[tm], bhf[tn]);
                }
        }

        __syncthreads();
        if (more) {
            stores(na, nb);
            __syncthreads();
        }
    }

#pragma unroll
    for (int tm = 0; tm < 4; tm++) {
#pragma unroll
        for (int tn = 0; tn < 4; tn++) {
            int e = warp_n * 32 + tn * 8 + 2 * tig;
#pragma unroll
            for (int half = 0; half < 2; half++) {
                int i = m0 + warp_m * 64 + tm * 16 + g + half * 8;
                *(float2*)&g_Y[((size_t)b * SEQ + i) * DIM + h * DH + e] =
                    make_float2(acc[tm][tn][2 * half], acc[tm][tn][2 * half + 1]);
            }
        }
    }
}

// ---------------- launch ----------------
extern "C" void kernel_launch(void* const* d_in, const int* in_sizes, int n_in,
                              void* d_out, int out_size)
{
    const float* x    = (const float*)d_in[0];
    const int*   mask = (const int*)d_in[1];
    const float* Wq   = (const float*)d_in[2];
    const float* Wk   = (const float*)d_in[3];
    const float* Wv   = (const float*)d_in[4];
    const float* Wout = (const float*)d_in[5];
    float* out = (float*)d_out;

    float* Yp;
    cudaGetSymbolAddress((void**)&Yp, g_Y);

    const int M = BS * SEQ;                                   // 8192
    const size_t out_elems = (size_t)BS * SEQ * DIM;          // 8388608
    const size_t att_elems = (size_t)BS * SEQ * SEQ;          // 16777216
    int write_att = ((size_t)out_size >= out_elems + att_elems) ? 1 : 0;

    invf_kernel<<<4, 256>>>();
    ap_kernel<<<(SEQ * SEQ + 255) / 256, 256>>>();

    // merged QKV projection: grid.z picks Wq/Wk/Wv and g_Q/g_K/g_V
    gemm_nt_tc<1, DIM><<<dim3(DIM / 128, M / 128, 3), 256>>>(
        x, Wq, nullptr, M, DIM, nullptr, Wk, Wv);

    gemm_nt_tc<2, DH><<<dim3(SEQ / 128, SEQ / 128, BH), 256>>>(
        nullptr, nullptr, nullptr, SEQ, SEQ, mask, nullptr, nullptr);

    softmax_kernel<<<BH * SEQ, 256>>>(out + out_elems, write_att);

    atv_tc<<<dim3(SEQ / 128, BH), 256>>>();

    gemm_nt_tc<0, DIM><<<dim3(DIM / 128, M / 128), 256>>>(
        Yp, Wout, out, M, DIM, nullptr, nullptr, nullptr);
}

// round 12
// speedup vs baseline: 1.5210x; 1.5210x over previous
#include <cuda_runtime.h>
#include <cuda_bf16.h>
#include <math.h>
#include <stdint.h>

#define BS    4
#define SEQ   2048
#define DIM   1024
#define NHEAD 8
#define DH    128
#define BH    (BS*NHEAD)
#define NEG_INF_F (-1e9f)

// ---------------- scratch (device globals; no runtime allocation) ----------------
__device__ float g_Q[(size_t)BS*NHEAD*SEQ*DH];      // 32 MB
__device__ float g_K[(size_t)BS*NHEAD*SEQ*DH];      // 32 MB
__device__ float g_V[(size_t)BS*NHEAD*SEQ*DH];      // 32 MB
__device__ float g_Y[(size_t)BS*SEQ*DIM];           // 32 MB
__device__ float g_AP[(size_t)SEQ*SEQ];             // 16 MB
__device__ float g_E[(size_t)BS*NHEAD*SEQ*SEQ];     // 512 MB
__device__ double g_invf[1024];                     // i in [0, SEQ/2)

// ---------------- helpers ----------------
__device__ __forceinline__ uint32_t pack_hi(float x, float y) {
    __nv_bfloat162 h = __floats2bfloat162_rn(x, y);
    return *reinterpret_cast<uint32_t*>(&h);
}
__device__ __forceinline__ uint32_t pack_lo(float x, float y, uint32_t hi) {
    __nv_bfloat162 h = *reinterpret_cast<__nv_bfloat162*>(&hi);
    __nv_bfloat162 l = __floats2bfloat162_rn(x - __bfloat162float(h.x),
                                             y - __bfloat162float(h.y));
    return *reinterpret_cast<uint32_t*>(&l);
}

__device__ __forceinline__ void mma16(float* c, const uint32_t* a, const uint32_t* b) {
    asm volatile(
        "mma.sync.aligned.m16n8k16.row.col.f32.bf16.bf16.f32 "
        "{%0,%1,%2,%3}, {%4,%5,%6,%7}, {%8,%9}, {%0,%1,%2,%3};\n"
        : "+f"(c[0]), "+f"(c[1]), "+f"(c[2]), "+f"(c[3])
        : "r"(a[0]), "r"(a[1]), "r"(a[2]), "r"(a[3]), "r"(b[0]), "r"(b[1]));
}

__device__ __forceinline__ void ldsm_x4(uint32_t* r, uint32_t addr) {
    asm volatile("ldmatrix.sync.aligned.m8n8.x4.shared.b16 {%0,%1,%2,%3}, [%4];"
                 : "=r"(r[0]), "=r"(r[1]), "=r"(r[2]), "=r"(r[3]) : "r"(addr));
}
__device__ __forceinline__ void ldsm_x2(uint32_t* r, uint32_t addr) {
    asm volatile("ldmatrix.sync.aligned.m8n8.x2.shared.b16 {%0,%1}, [%2];"
                 : "=r"(r[0]), "=r"(r[1]) : "r"(addr));
}

// ---------------- AP precompute ----------------
__global__ void invf_kernel() {
    int i = blockIdx.x * blockDim.x + threadIdx.x;
    if (i < 1024) g_invf[i] = exp(-(double)(2 * i) / 1024.0 * log(10000.0));
}
__global__ void ap_kernel() {
    int idx = blockIdx.x * blockDim.x + threadIdx.x;
    if (idx >= SEQ * SEQ) return;
    int q = idx >> 11;
    int k = idx & (SEQ - 1);
    double angle = (double)q * g_invf[k >> 1];
    const double TWO_PI = 6.283185307179586476925286766559;
    double t = floor(angle * (1.0 / TWO_PI));
    float a = (float)(angle - t * TWO_PI);
    g_AP[idx] = (k & 1) ? cosf(a) : sinf(a);
}

// ======================== NT tensor-core GEMM (3x bf16 compensated, ldmatrix) ========================
// C[M,N] = A[M,K] * B[N,K]^T ; smem holds PACKED bf16x2 hi/lo; ldmatrix frags.
// MODE 0: row-major store
// MODE 1: merged QKV: blockIdx.z selects weight and dest, scatter store
#define RS 20   // smem row stride in words (16 data + pad; ≡4 mod 32 → conflict-free)
template<int MODE>
__global__ __launch_bounds__(256, 1)
void gemm_nt_tc(const float* __restrict__ Ag, const float* __restrict__ Bg,
                float* __restrict__ Cg, int M, int N, int K,
                const float* __restrict__ W1, const float* __restrict__ W2)
{
    __shared__ __align__(16) uint32_t AhiS[128 * RS];
    __shared__ __align__(16) uint32_t AloS[128 * RS];
    __shared__ __align__(16) uint32_t BhiS[128 * RS];
    __shared__ __align__(16) uint32_t BloS[128 * RS];

    const int tid  = threadIdx.x;
    const int lane = tid & 31;
    const int wid  = tid >> 5;
    const int g    = lane >> 2;
    const int tig  = lane & 3;
    const int warp_m = wid & 1;    // 2 warp rows of 64
    const int warp_n = wid >> 1;   // 4 warp cols of 32

    const int m0 = blockIdx.y * 128;
    const int n0 = blockIdx.x * 128;

    const float* A = Ag;
    const float* B = Bg;
    float* Cd = Cg;
    if (MODE == 1) {
        int z = blockIdx.z;
        B  = (z == 0) ? Bg : (z == 1) ? W1 : W2;
        Cd = (z == 0) ? g_Q : (z == 1) ? g_K : g_V;
    }

    float acc[4][4][4];
#pragma unroll
    for (int i = 0; i < 4; i++)
#pragma unroll
        for (int j = 0; j < 4; j++)
#pragma unroll
            for (int r = 0; r < 4; r++) acc[i][j][r] = 0.f;

    const int ldr = tid >> 3;          // 0..31 (+r*32)
    const int ldc = (tid & 7) * 4;     // float col (4-wide) within 32-k chunk
    const int wc  = (tid & 7) * 2;     // word col

    const uint32_t AhiB = (uint32_t)__cvta_generic_to_shared(AhiS);
    const uint32_t AloB = (uint32_t)__cvta_generic_to_shared(AloS);
    const uint32_t BhiB = (uint32_t)__cvta_generic_to_shared(BhiS);
    const uint32_t BloB = (uint32_t)__cvta_generic_to_shared(BloS);
    const int a_row  = lane & 15;
    const int a_koff = (lane >> 4) << 2;
    const int b_row  = lane & 7;
    const int b_koff = ((lane >> 3) & 1) << 2;

    auto loadg = [&](int k0, float4* pa, float4* pb) {
#pragma unroll
        for (int r = 0; r < 4; r++) {
            int row = ldr + r * 32;
            pa[r] = *(const float4*)&A[(size_t)(m0 + row) * K + k0 + ldc];
            pb[r] = *(const float4*)&B[(size_t)(n0 + row) * K + k0 + ldc];
        }
    };
    auto stores = [&](const float4* pa, const float4* pb) {
#pragma unroll
        for (int r = 0; r < 4; r++) {
            int row = ldr + r * 32;
            float4 va = pa[r], vb = pb[r];
            uint32_t ah0 = pack_hi(va.x, va.y), ah1 = pack_hi(va.z, va.w);
            uint32_t al0 = pack_lo(va.x, va.y, ah0), al1 = pack_lo(va.z, va.w, ah1);
            uint32_t bh0 = pack_hi(vb.x, vb.y), bh1 = pack_hi(vb.z, vb.w);
            uint32_t bl0 = pack_lo(vb.x, vb.y, bh0), bl1 = pack_lo(vb.z, vb.w, bh1);
            *(uint2*)&AhiS[row * RS + wc] = make_uint2(ah0, ah1);
            *(uint2*)&AloS[row * RS + wc] = make_uint2(al0, al1);
            *(uint2*)&BhiS[row * RS + wc] = make_uint2(bh0, bh1);
            *(uint2*)&BloS[row * RS + wc] = make_uint2(bl0, bl1);
        }
    };

    float4 pa[4], pb[4];
    loadg(0, pa, pb);
    stores(pa, pb);
    __syncthreads();

    for (int k0 = 0; k0 < K; k0 += 32) {
        const bool more = (k0 + 32 < K);
        float4 na[4], nb[4];
        if (more) loadg(k0 + 32, na, nb);

#pragma unroll
        for (int ks = 0; ks < 2; ks++) {
            const int wb = ks * 8;
            uint32_t ahf[4][4], alf[4][4], bhf[4][2], blf[4][2];
#pragma unroll
            for (int tm = 0; tm < 4; tm++) {
                int mr = warp_m * 64 + tm * 16;
                uint32_t off = (uint32_t)(((mr + a_row) * RS + wb + a_koff) * 4);
                ldsm_x4(ahf[tm], AhiB + off);
                ldsm_x4(alf[tm], AloB + off);
            }
#pragma unroll
            for (int tn = 0; tn < 4; tn++) {
                int nr = warp_n * 32 + tn * 8;
                uint32_t off = (uint32_t)(((nr + b_row) * RS + wb + b_koff) * 4);
                ldsm_x2(bhf[tn], BhiB + off);
                ldsm_x2(blf[tn], BloB + off);
            }
#pragma unroll
            for (int tm = 0; tm < 4; tm++)
#pragma unroll
                for (int tn = 0; tn < 4; tn++) {
                    mma16(acc[tm][tn], ahf[tm], bhf[tn]);
                    mma16(acc[tm][tn], ahf[tm], blf[tn]);
                    mma16(acc[tm][tn], alf[tm], bhf[tn]);
                }
        }

        __syncthreads();
        if (more) {
            stores(na, nb);
            __syncthreads();
        }
    }

    // ---------------- epilogue ----------------
    if (MODE == 0) {
#pragma unroll
        for (int tm = 0; tm < 4; tm++) {
#pragma unroll
            for (int tn = 0; tn < 4; tn++) {
                int row0 = m0 + warp_m * 64 + tm * 16 + g;
                int col  = n0 + warp_n * 32 + tn * 8 + 2 * tig;
                *(float2*)&Cd[(size_t)row0 * N + col]       = make_float2(acc[tm][tn][0], acc[tm][tn][1]);
                *(float2*)&Cd[(size_t)(row0 + 8) * N + col] = make_float2(acc[tm][tn][2], acc[tm][tn][3]);
            }
        }
    } else {
#pragma unroll
        for (int tm = 0; tm < 4; tm++) {
#pragma unroll
            for (int tn = 0; tn < 4; tn++) {
                int col = n0 + warp_n * 32 + tn * 8 + 2 * tig;
                int h = col >> 7, e = col & (DH - 1);
#pragma unroll
                for (int half = 0; half < 2; half++) {
                    int row = m0 + warp_m * 64 + tm * 16 + g + half * 8;
                    int b = row >> 11, nr = row & (SEQ - 1);
                    *(float2*)&Cd[(((size_t)b * NHEAD + h) * SEQ + nr) * DH + e] =
                        make_float2(acc[tm][tn][2 * half], acc[tm][tn][2 * half + 1]);
                }
            }
        }
    }
}

// ======================== QK^T: Q-resident strip kernel ========================
// Block: 64 q-rows (resident, packed bf16 hi/lo, full K=128) x 512 k-cols (4 tiles
// of 128, K streamed in 16-k chunks with 1-ahead prefetch). 2 CTAs/SM.
#define AS2 68   // A row stride in words (64 data + 4 pad; 272B ≡0 mod 16 for ldmatrix, ≡4 mod 32 banks)
#define BS2 12   // B row stride in words (8 data + 4 pad; 48B ≡0 mod 16)
#define QKNT 4
__global__ __launch_bounds__(256, 2)
void qk_tc(const int* __restrict__ mask)
{
    __shared__ __align__(16) uint32_t AhiS[64 * AS2];
    __shared__ __align__(16) uint32_t AloS[64 * AS2];
    __shared__ __align__(16) uint32_t BhiS[128 * BS2];
    __shared__ __align__(16) uint32_t BloS[128 * BS2];
    __shared__ unsigned char maskS[576];   // [0,64): q rows; [64,576): 512 k cols

    const int tid  = threadIdx.x;
    const int lane = tid & 31;
    const int wid  = tid >> 5;
    const int g    = lane >> 2;
    const int tig  = lane & 3;
    const int warp_m = wid & 1;    // 2 x 32 q-rows
    const int warp_n = wid >> 1;   // 4 x 32 k-cols

    const int m0    = blockIdx.y * 64;
    const int nbase = blockIdx.x * 512;
    const int bh    = blockIdx.z;
    const int bb    = bh >> 3;

    const float* Qp = g_Q + (size_t)bh * SEQ * DH;
    const float* Kp = g_K + (size_t)bh * SEQ * DH;
    float* Ep = g_E + (size_t)bh * SEQ * SEQ;

    // mask preload
    for (int i = tid; i < 576; i += 256)
        maskS[i] = (unsigned char)((i < 64) ? mask[bb * SEQ + m0 + i]
                                            : mask[bb * SEQ + nbase + (i - 64)]);

    // resident Q tile: 64 rows x 128 floats, packed hi/lo
    {
        int row = tid >> 2;
#pragma unroll
        for (int j = 0; j < 8; j++) {
            int c4 = (tid & 3) + j * 4;            // float4 idx 0..31
            float4 v = *(const float4*)&Qp[(size_t)(m0 + row) * DH + c4 * 4];
            uint32_t h0 = pack_hi(v.x, v.y), h1 = pack_hi(v.z, v.w);
            uint32_t l0 = pack_lo(v.x, v.y, h0), l1 = pack_lo(v.z, v.w, h1);
            *(uint2*)&AhiS[row * AS2 + c4 * 2] = make_uint2(h0, h1);
            *(uint2*)&AloS[row * AS2 + c4 * 2] = make_uint2(l0, l1);
        }
    }

    const uint32_t AhiB = (uint32_t)__cvta_generic_to_shared(AhiS);
    const uint32_t AloB = (uint32_t)__cvta_generic_to_shared(AloS);
    const uint32_t BhiB = (uint32_t)__cvta_generic_to_shared(BhiS);
    const uint32_t BloB = (uint32_t)__cvta_generic_to_shared(BloS);
    const int a_row  = lane & 15;
    const int a_koff = (lane >> 4) << 2;
    const int b_row  = lane & 7;
    const int b_koff = ((lane >> 3) & 1) << 2;

    auto loadB = [&](int it, float4* pb) {
        int t = it >> 3, kc = it & 7;
        int row = tid >> 1;
        int c4 = (tid & 1) * 2;
        const float* base = &Kp[(size_t)(nbase + t * 128 + row) * DH + kc * 16];
        pb[0] = *(const float4*)&base[c4 * 4];
        pb[1] = *(const float4*)&base[(c4 + 1) * 4];
    };
    auto storeB = [&](const float4* pb) {
        int row = tid >> 1;
        int wc = (tid & 1) * 4;
#pragma unroll
        for (int j = 0; j < 2; j++) {
            float4 v = pb[j];
            uint32_t h0 = pack_hi(v.x, v.y), h1 = pack_hi(v.z, v.w);
            uint32_t l0 = pack_lo(v.x, v.y, h0), l1 = pack_lo(v.z, v.w, h1);
            *(uint2*)&BhiS[row * BS2 + wc + 2 * j] = make_uint2(h0, h1);
            *(uint2*)&BloS[row * BS2 + wc + 2 * j] = make_uint2(l0, l1);
        }
    };

    float acc[2][4][4];
#pragma unroll
    for (int i = 0; i < 2; i++)
#pragma unroll
        for (int j = 0; j < 4; j++)
#pragma unroll
            for (int r = 0; r < 4; r++) acc[i][j][r] = 0.f;

    float4 pb[2];
    loadB(0, pb);
    storeB(pb);
    __syncthreads();

#pragma unroll 1
    for (int it = 0; it < QKNT * 8; it++) {
        const int t = it >> 3, kc = it & 7;
        const bool more = (it + 1 < QKNT * 8);
        float4 nb[2];
        if (more) loadB(it + 1, nb);

        uint32_t ahf[2][4], alf[2][4], bhf[4][2], blf[4][2];
#pragma unroll
        for (int tm = 0; tm < 2; tm++) {
            int mr = warp_m * 32 + tm * 16;
            uint32_t off = (uint32_t)(((mr + a_row) * AS2 + kc * 8 + a_koff) * 4);
            ldsm_x4(ahf[tm], AhiB + off);
            ldsm_x4(alf[tm], AloB + off);
        }
#pragma unroll
        for (int tn = 0; tn < 4; tn++) {
            int nr = warp_n * 32 + tn * 8;
            uint32_t off = (uint32_t)(((nr + b_row) * BS2 + b_koff) * 4);
            ldsm_x2(bhf[tn], BhiB + off);
            ldsm_x2(blf[tn], BloB + off);
        }
#pragma unroll
        for (int tm = 0; tm < 2; tm++)
#pragma unroll
            for (int tn = 0; tn < 4; tn++) {
                mma16(acc[tm][tn], ahf[tm], bhf[tn]);
                mma16(acc[tm][tn], ahf[tm], blf[tn]);
                mma16(acc[tm][tn], alf[tm], bhf[tn]);
            }

        __syncthreads();
        if (more) {
            storeB(nb);
            __syncthreads();
        }

        if (kc == 7) {
            // epilogue for tile t: AP + mask -> g_E
            int n0t = nbase + t * 128;
#pragma unroll
            for (int tm = 0; tm < 2; tm++) {
#pragma unroll
                for (int half = 0; half < 2; half++) {
                    int qi = warp_m * 32 + tm * 16 + g + half * 8;
                    int q = m0 + qi;
                    int mq = maskS[qi];
#pragma unroll
                    for (int tn = 0; tn < 4; tn++) {
                        int ci = warp_n * 32 + tn * 8 + 2 * tig;
                        int c = n0t + ci;
                        int mk0 = maskS[64 + t * 128 + ci];
                        int mk1 = maskS[64 + t * 128 + ci + 1];
                        float2 ap = *(const float2*)&g_AP[(size_t)q * SEQ + c];
                        float v0 = (mq && mk0) ? acc[tm][tn][2 * half]     + ap.x : NEG_INF_F;
                        float v1 = (mq && mk1) ? acc[tm][tn][2 * half + 1] + ap.y : NEG_INF_F;
                        *(float2*)&Ep[(size_t)q * SEQ + c] = make_float2(v0, v1);
                    }
                }
            }
#pragma unroll
            for (int i = 0; i < 2; i++)
#pragma unroll
                for (int j = 0; j < 4; j++)
#pragma unroll
                    for (int r = 0; r < 4; r++) acc[i][j][r] = 0.f;
        }
    }
}

// ======================== softmax (float4) ========================
__global__ __launch_bounds__(256)
void softmax_kernel(float* __restrict__ att_out, int write_att)
{
    int row = blockIdx.x;
    float4* Ep4 = (float4*)(g_E + (size_t)row * SEQ);
    int tid = threadIdx.x;

    __shared__ float shm[8];
    __shared__ float shs[8];

    float4 u0 = Ep4[tid];
    float4 u1 = Ep4[tid + 256];
    float mx = fmaxf(fmaxf(fmaxf(u0.x, u0.y), fmaxf(u0.z, u0.w)),
                     fmaxf(fmaxf(u1.x, u1.y), fmaxf(u1.z, u1.w)));
#pragma unroll
    for (int o = 16; o > 0; o >>= 1) mx = fmaxf(mx, __shfl_xor_sync(0xffffffffu, mx, o));
    int w = tid >> 5, l = tid & 31;
    if (l == 0) shm[w] = mx;
    __syncthreads();
    float rmax = shm[0];
#pragma unroll
    for (int i = 1; i < 8; i++) rmax = fmaxf(rmax, shm[i]);

    u0.x = expf(u0.x - rmax); u0.y = expf(u0.y - rmax);
    u0.z = expf(u0.z - rmax); u0.w = expf(u0.w - rmax);
    u1.x = expf(u1.x - rmax); u1.y = expf(u1.y - rmax);
    u1.z = expf(u1.z - rmax); u1.w = expf(u1.w - rmax);
    float s = (u0.x + u0.y + u0.z + u0.w) + (u1.x + u1.y + u1.z + u1.w);
#pragma unroll
    for (int o = 16; o > 0; o >>= 1) s += __shfl_xor_sync(0xffffffffu, s, o);
    if (l == 0) shs[w] = s;
    __syncthreads();
    float rsum = 0.f;
#pragma unroll
    for (int i = 0; i < 8; i++) rsum += shs[i];

    float inv = 1.f / rsum;
    u0.x *= inv; u0.y *= inv; u0.z *= inv; u0.w *= inv;
    u1.x *= inv; u1.y *= inv; u1.z *= inv; u1.w *= inv;

    Ep4[tid]       = u0;
    Ep4[tid + 256] = u1;

    int h = (row >> 11) & (NHEAD - 1);
    if (write_att && h == NHEAD - 1) {
        int b = row >> 14;
        int q = row & (SEQ - 1);
        float4* ap4 = (float4*)(att_out + ((size_t)b * SEQ + q) * SEQ);
        ap4[tid]       = u0;
        ap4[tid + 256] = u1;
    }
}

// ======================== A^T V (TN, 3x bf16 compensated, packed smem) ========================
#define MS 136  // m stride in words (128 + pad)
__global__ __launch_bounds__(256, 1)
void atv_tc()
{
    __shared__ __align__(16) uint32_t AhiS[16 * MS];
    __shared__ __align__(16) uint32_t AloS[16 * MS];
    __shared__ __align__(16) uint32_t BhiS[16 * MS];
    __shared__ __align__(16) uint32_t BloS[16 * MS];

    const int tid  = threadIdx.x;
    const int lane = tid & 31;
    const int wid  = tid >> 5;
    const int g    = lane >> 2;
    const int tig  = lane & 3;
    const int warp_m = wid & 1;
    const int warp_n = wid >> 1;

    const int bh = blockIdx.y;
    const int b = bh >> 3, h = bh & 7;
    const int m0 = blockIdx.x * 128;

    const float* Ap = g_E + (size_t)bh * SEQ * SEQ;
    const float* Vp = g_V + (size_t)bh * SEQ * DH;

    float acc[4][4][4];
#pragma unroll
    for (int i = 0; i < 4; i++)
#pragma unroll
        for (int j = 0; j < 4; j++)
#pragma unroll
            for (int r = 0; r < 4; r++) acc[i][j][r] = 0.f;

    const int pbase = tid >> 5;
    const int mc    = (tid & 31) * 4;

    auto loadg = [&](int k0, float4* pa, float4* pb) {
#pragma unroll
        for (int r = 0; r < 2; r++) {
            int p = pbase + r * 8;
            pa[2 * r + 0] = *(const float4*)&Ap[(size_t)(k0 + 2 * p)     * SEQ + m0 + mc];
            pa[2 * r + 1] = *(const float4*)&Ap[(size_t)(k0 + 2 * p + 1) * SEQ + m0 + mc];
            pb[2 * r + 0] = *(const float4*)&Vp[(size_t)(k0 + 2 * p)     * DH + mc];
            pb[2 * r + 1] = *(const float4*)&Vp[(size_t)(k0 + 2 * p + 1) * DH + mc];
        }
    };
    auto stores = [&](const float4* pa, const float4* pb) {
#pragma unroll
        for (int r = 0; r < 2; r++) {
            int p = pbase + r * 8;
            float4 a0 = pa[2 * r], a1 = pa[2 * r + 1];
            float4 b0 = pb[2 * r], b1 = pb[2 * r + 1];
            uint32_t ah0 = pack_hi(a0.x, a1.x), ah1 = pack_hi(a0.y, a1.y);
            uint32_t ah2 = pack_hi(a0.z, a1.z), ah3 = pack_hi(a0.w, a1.w);
            uint32_t al0 = pack_lo(a0.x, a1.x, ah0), al1 = pack_lo(a0.y, a1.y, ah1);
            uint32_t al2 = pack_lo(a0.z, a1.z, ah2), al3 = pack_lo(a0.w, a1.w, ah3);
            uint32_t bh0 = pack_hi(b0.x, b1.x), bh1 = pack_hi(b0.y, b1.y);
            uint32_t bh2 = pack_hi(b0.z, b1.z), bh3 = pack_hi(b0.w, b1.w);
            uint32_t bl0 = pack_lo(b0.x, b1.x, bh0), bl1 = pack_lo(b0.y, b1.y, bh1);
            uint32_t bl2 = pack_lo(b0.z, b1.z, bh2), bl3 = pack_lo(b0.w, b1.w, bh3);
            *(uint4*)&AhiS[p * MS + mc] = make_uint4(ah0, ah1, ah2, ah3);
            *(uint4*)&AloS[p * MS + mc] = make_uint4(al0, al1, al2, al3);
            *(uint4*)&BhiS[p * MS + mc] = make_uint4(bh0, bh1, bh2, bh3);
            *(uint4*)&BloS[p * MS + mc] = make_uint4(bl0, bl1, bl2, bl3);
        }
    };

    float4 pa[4], pb[4];
    loadg(0, pa, pb);
    stores(pa, pb);
    __syncthreads();

    for (int k0 = 0; k0 < SEQ; k0 += 32) {
        const bool more = (k0 + 32 < SEQ);
        float4 na[4], nb[4];
        if (more) loadg(k0 + 32, na, nb);

#pragma unroll
        for (int ks = 0; ks < 2; ks++) {
            const int wb = ks * 8;
            uint32_t ahf[4][4], alf[4][4], bhf[4][2], blf[4][2];
#pragma unroll
            for (int tm = 0; tm < 4; tm++) {
                int m = warp_m * 64 + tm * 16 + g;
                const uint32_t* ph = &AhiS[(wb + tig) * MS + m];
                const uint32_t* pl = &AloS[(wb + tig) * MS + m];
                ahf[tm][0] = ph[0];
                ahf[tm][1] = ph[8];
                ahf[tm][2] = ph[4 * MS];
                ahf[tm][3] = ph[4 * MS + 8];
                alf[tm][0] = pl[0];
                alf[tm][1] = pl[8];
                alf[tm][2] = pl[4 * MS];
                alf[tm][3] = pl[4 * MS + 8];
            }
#pragma unroll
            for (int tn = 0; tn < 4; tn++) {
                int n = warp_n * 32 + tn * 8 + g;
                const uint32_t* qh = &BhiS[(wb + tig) * MS + n];
                const uint32_t* ql = &BloS[(wb + tig) * MS + n];
                bhf[tn][0] = qh[0];
                bhf[tn][1] = qh[4 * MS];
                blf[tn][0] = ql[0];
                blf[tn][1] = ql[4 * MS];
            }
#pragma unroll
            for (int tm = 0; tm < 4; tm++)
#pragma unroll
                for (int tn = 0; tn < 4; tn++) {
                    mma16(acc[tm][tn], ahf[tm], bhf[tn]);
                    mma16(acc[tm][tn], ahf[tm], blf[tn]);
                    mma16(acc[tm][tn], alf[tm], bhf[tn]);
                }
        }

        __syncthreads();
        if (more) {
            stores(na, nb);
            __syncthreads();
        }
    }

#pragma unroll
    for (int tm = 0; tm < 4; tm++) {
#pragma unroll
        for (int tn = 0; tn < 4; tn++) {
            int e = warp_n * 32 + tn * 8 + 2 * tig;
#pragma unroll
            for (int half = 0; half < 2; half++) {
                int i = m0 + warp_m * 64 + tm * 16 + g + half * 8;
                *(float2*)&g_Y[((size_t)b * SEQ + i) * DIM + h * DH + e] =
                    make_float2(acc[tm][tn][2 * half], acc[tm][tn][2 * half + 1]);
            }
        }
    }
}

// ---------------- launch ----------------
extern "C" void kernel_launch(void* const* d_in, const int* in_sizes, int n_in,
                              void* d_out, int out_size)
{
    const float* x    = (const float*)d_in[0];
    const int*   mask = (const int*)d_in[1];
    const float* Wq   = (const float*)d_in[2];
    const float* Wk   = (const float*)d_in[3];
    const float* Wv   = (const float*)d_in[4];
    const float* Wout = (const float*)d_in[5];
    float* out = (float*)d_out;

    float* Yp;
    cudaGetSymbolAddress((void**)&Yp, g_Y);

    const int M = BS * SEQ;                                   // 8192
    const size_t out_elems = (size_t)BS * SEQ * DIM;          // 8388608
    const size_t att_elems = (size_t)BS * SEQ * SEQ;          // 16777216
    int write_att = ((size_t)out_size >= out_elems + att_elems) ? 1 : 0;

    invf_kernel<<<4, 256>>>();
    ap_kernel<<<(SEQ * SEQ + 255) / 256, 256>>>();

    // merged QKV projection
    gemm_nt_tc<1><<<dim3(DIM / 128, M / 128, 3), 256>>>(
        x, Wq, nullptr, M, DIM, DIM, Wk, Wv);

    // QK^T + AP + mask (Q-resident strips)
    qk_tc<<<dim3(SEQ / 512, SEQ / 64, BH), 256>>>(mask);

    softmax_kernel<<<BH * SEQ, 256>>>(out + out_elems, write_att);

    atv_tc<<<dim3(SEQ / 128, BH), 256>>>();

    gemm_nt_tc<0><<<dim3(DIM / 128, M / 128), 256>>>(
        Yp, Wout, out, M, DIM, DIM, nullptr, nullptr);
}